// round 10
// baseline (speedup 1.0000x reference)
#include <cuda_runtime.h>
#include <cuda_fp16.h>

// Problem constants
#define NXv 128
#define NYv 128
#define NZv 8
#define NVOX (NXv * NYv * NZv)   // 131072
#define NVIEW 6
#define NCH 64
#define HFv 116
#define WFv 200
#define FEAT_HW (HFv * WFv)      // 23200
#define IMG_W 1600.0f
#define IMG_H 928.0f

#define PTS_PER_BLK 32           // 256 threads / 8 lanes-per-point

// Channel-last fp16 scratch: [V, HF, WF, C]  (17.8 MB). One tap = 128B line.
__device__ __align__(256) static __half g_feat_h[NVIEW * FEAT_HW * NCH];

// ---------------------------------------------------------------------------
// Kernel 1: transpose+convert [V,C,H,W] fp32 -> [V,H,W,C] fp16.
// ---------------------------------------------------------------------------
__global__ __launch_bounds__(256)
void convert_kernel(const float* __restrict__ xfov)
{
    __shared__ float tile[NCH][33];

    const int w0 = blockIdx.x * 32;
    const int vh = blockIdx.y;            // 0..695
    const int v  = vh / HFv;
    const int h  = vh - v * HFv;

    const int tx = threadIdx.x & 31;
    const int ty = threadIdx.x >> 5;      // 0..7

    const int w = w0 + tx;
    if (w < WFv) {
#pragma unroll
        for (int i = 0; i < 8; i++) {
            const int c = ty + i * 8;
            tile[c][tx] = xfov[((size_t)(v * NCH + c) * HFv + h) * WFv + w];
        }
    }
    __syncthreads();

    __half2* dst = (__half2*)g_feat_h;
#pragma unroll
    for (int j = 0; j < 4; j++) {
        const int ww = w0 + ty + 8 * j;
        if (ww < WFv) {
            const float a = tile[2 * tx + 0][ty + 8 * j];
            const float b = tile[2 * tx + 1][ty + 8 * j];
            dst[(size_t)(v * FEAT_HW + h * WFv + ww) * (NCH / 2) + tx] =
                __floats2half2_rn(a, b);
        }
    }
}

// ---------------------------------------------------------------------------
// Kernel 2: gather. 8 lanes per point (8 channels each).
// One LDG.128 = 4 points x 1 full tap line -> minimal L1 wavefronts.
// Output staged in SMEM for 128B-coalesced stores.
// ---------------------------------------------------------------------------
__global__ __launch_bounds__(256)
void gather_kernel(const float* __restrict__ points,
                   const float* __restrict__ proj,
                   float* __restrict__ out)
{
    __shared__ float sM[NVIEW * 16];
    __shared__ float s_out[PTS_PER_BLK * 65];   // stride 65: conflict-free

    if (threadIdx.x < NVIEW * 16) sM[threadIdx.x] = proj[threadIdx.x];
    __syncthreads();

    const int q  = threadIdx.x & 7;            // channel-eighth (8 ch)
    const int pl = threadIdx.x >> 3;           // local point 0..31
    const int p  = blockIdx.x * PTS_PER_BLK + pl;  // output-linear voxel

    const int z = p & (NZv - 1);
    const int y = (p >> 3) & (NYv - 1);
    const int x = p >> 10;
    const int n = (z * NYv + y) * NXv + x;

    const float pxw = __ldg(points + n * 3 + 0);
    const float pyw = __ldg(points + n * 3 + 1);
    const float pzw = __ldg(points + n * 3 + 2);

    float acc[8];
#pragma unroll
    for (int i = 0; i < 8; i++) acc[i] = 0.0f;
    int cnt = 0;

    const int coff = q * 8;   // channel offset in halves (16B-aligned)

#pragma unroll 1
    for (int v = 0; v < NVIEW; v++) {
        const float* M = &sM[v * 16];
        const float cx = fmaf(M[0], pxw, fmaf(M[1], pyw, fmaf(M[2],  pzw, M[3])));
        const float cy = fmaf(M[4], pxw, fmaf(M[5], pyw, fmaf(M[6],  pzw, M[7])));
        const float d  = fmaf(M[8], pxw, fmaf(M[9], pyw, fmaf(M[10], pzw, M[11])));

        const float ds = (fabsf(d) > 1e-6f) ? d : 1e-6f;
        const float r  = __fdividef(1.0f, ds);
        const float u  = cx * r;
        const float vv = cy * r;

        const bool valid = (d > 0.0f) & (u > 0.0f) & (u < IMG_W)
                                      & (vv > 0.0f) & (vv < IMG_H);
        if (!valid) continue;

        // Exact power-of-2 scale: WF/IMG_W = HF/IMG_H = 0.125
        const float fx = fmaf(u,  0.125f, -0.5f);   // (-0.5, 199.5)
        const float fy = fmaf(vv, 0.125f, -0.5f);   // (-0.5, 115.5)
        const float x0f = floorf(fx);
        const float y0f = floorf(fy);
        const int x0 = (int)x0f;   // [-1, 199]
        const int y0 = (int)y0f;   // [-1, 115]
        const float wx1 = fx - x0f;
        const float wy1 = fy - y0f;

        // Base clamped so all 4 taps are in-bounds; edge handling folded
        // into weights (identical to zero-padded bilinear).
        const int bx = min(max(x0, 0), WFv - 2);
        const int by = min(max(y0, 0), HFv - 2);
        const float wl = (x0 < 0) ? wx1 : ((x0 >= WFv - 1) ? 0.0f : 1.0f - wx1);
        const float wr = (x0 < 0) ? 0.0f : ((x0 >= WFv - 1) ? 1.0f - wx1 : wx1);
        const float wt = (y0 < 0) ? wy1 : ((y0 >= HFv - 1) ? 0.0f : 1.0f - wy1);
        const float wb = (y0 < 0) ? 0.0f : ((y0 >= HFv - 1) ? 1.0f - wy1 : wy1);

        const __half2 hw00 = __float2half2_rn(wl * wt);
        const __half2 hw10 = __float2half2_rn(wr * wt);
        const __half2 hw01 = __float2half2_rn(wl * wb);
        const __half2 hw11 = __float2half2_rn(wr * wb);

        const __half* bp = g_feat_h
            + (unsigned)((v * FEAT_HW + by * WFv + bx) * NCH) + coff;

        // 4 LDG.128: one per tap. Within a warp each instr covers 4 points
        // x one full 128B line -> 4 wavefronts/instr, zero replay waste.
        const uint4 t00 = __ldg((const uint4*)(bp));
        const uint4 t10 = __ldg((const uint4*)(bp + NCH));
        const uint4 t01 = __ldg((const uint4*)(bp + WFv * NCH));
        const uint4 t11 = __ldg((const uint4*)(bp + (WFv + 1) * NCH));

        const __half2* f00 = (const __half2*)&t00;
        const __half2* f10 = (const __half2*)&t10;
        const __half2* f01 = (const __half2*)&t01;
        const __half2* f11 = (const __half2*)&t11;
#pragma unroll
        for (int k = 0; k < 4; k++) {
            __half2 s = __hmul2(f00[k], hw00);
            s = __hfma2(f10[k], hw10, s);
            s = __hfma2(f01[k], hw01, s);
            s = __hfma2(f11[k], hw11, s);
            const float2 sf = __half22float2(s);
            acc[2 * k + 0] += sf.x;
            acc[2 * k + 1] += sf.y;
        }
        cnt++;
    }

    // Stage normalized result in SMEM
    const float inv = (cnt > 0) ? (1.0f / (float)cnt) : 0.0f;
#pragma unroll
    for (int j = 0; j < 8; j++) {
        s_out[pl * 65 + coff + j] = acc[j] * inv;
    }
    __syncthreads();

    // Coalesced write-out: 2048 floats; 32 consecutive p per channel = 128B
    const int p0 = blockIdx.x * PTS_PER_BLK;
#pragma unroll
    for (int jj = 0; jj < 8; jj++) {
        const int idx = threadIdx.x + jj * 256;   // 0..2047
        const int c   = idx >> 5;                 // 0..63
        const int ppl = idx & 31;                 // 0..31
        out[(size_t)c * NVOX + p0 + ppl] = s_out[ppl * 65 + c];
    }
}

extern "C" void kernel_launch(void* const* d_in, const int* in_sizes, int n_in,
                              void* d_out, int out_size)
{
    const float* x_fov  = (const float*)d_in[0];  // [1,6,64,116,200]
    const float* points = (const float*)d_in[1];  // [131072,3]
    const float* proj   = (const float*)d_in[2];  // [6,4,4]
    float* out = (float*)d_out;                   // [1,64,128,128,8]

    {
        dim3 blk(256);
        dim3 grd((WFv + 31) / 32, NVIEW * HFv);   // (7, 696)
        convert_kernel<<<grd, blk>>>(x_fov);
    }
    {
        const int blocks = NVOX / PTS_PER_BLK;    // 4096
        gather_kernel<<<blocks, 256>>>(points, proj, out);
    }
}

// round 11
// speedup vs baseline: 1.0536x; 1.0536x over previous
#include <cuda_runtime.h>
#include <cuda_fp16.h>

// Problem constants
#define NXv 128
#define NYv 128
#define NZv 8
#define NVOX (NXv * NYv * NZv)   // 131072
#define NVIEW 6
#define NCH 64
#define HFv 116
#define WFv 200
#define FEAT_HW (HFv * WFv)      // 23200
#define IMG_W 1600.0f
#define IMG_H 928.0f

#define PTS_PER_BLK 32           // 256 threads / 8 lanes-per-point

// Channel-last fp16 scratch: [V, HF, WF, C]  (17.8 MB). One tap = 128B line.
__device__ __align__(256) static __half g_feat_h[NVIEW * FEAT_HW * NCH];

// ---------------------------------------------------------------------------
// Kernel 1: transpose+convert [V,C,H,W] fp32 -> [V,H,W,C] fp16.
// ---------------------------------------------------------------------------
__global__ __launch_bounds__(256)
void convert_kernel(const float* __restrict__ xfov)
{
    __shared__ float tile[NCH][33];

    const int w0 = blockIdx.x * 32;
    const int vh = blockIdx.y;            // 0..695
    const int v  = vh / HFv;
    const int h  = vh - v * HFv;

    const int tx = threadIdx.x & 31;
    const int ty = threadIdx.x >> 5;      // 0..7

    const int w = w0 + tx;
    if (w < WFv) {
#pragma unroll
        for (int i = 0; i < 8; i++) {
            const int c = ty + i * 8;
            tile[c][tx] = xfov[((size_t)(v * NCH + c) * HFv + h) * WFv + w];
        }
    }
    __syncthreads();

    __half2* dst = (__half2*)g_feat_h;
#pragma unroll
    for (int j = 0; j < 4; j++) {
        const int ww = w0 + ty + 8 * j;
        if (ww < WFv) {
            const float a = tile[2 * tx + 0][ty + 8 * j];
            const float b = tile[2 * tx + 1][ty + 8 * j];
            dst[(size_t)(v * FEAT_HW + h * WFv + ww) * (NCH / 2) + tx] =
                __floats2half2_rn(a, b);
        }
    }
}

// ---------------------------------------------------------------------------
// Kernel 2: gather. 8 lanes per point (8 channels each).
// Projection computed ONCE per (point,view): lane r (<6) owns view r,
// descriptors broadcast intra-octet via SHFL. Loads keep the R10 shape:
// one LDG.128 = 4 points x one full 128B tap line.
// ---------------------------------------------------------------------------
__global__ __launch_bounds__(256)
void gather_kernel(const float* __restrict__ points,
                   const float* __restrict__ proj,
                   float* __restrict__ out)
{
    __shared__ float sM[NVIEW * 16];
    __shared__ float s_out[PTS_PER_BLK * 65];   // stride 65: conflict-free

    if (threadIdx.x < NVIEW * 16) sM[threadIdx.x] = proj[threadIdx.x];
    __syncthreads();

    const int lane = threadIdx.x & 31;
    const int r    = lane & 7;                 // lane-in-octet
    const int obase = lane & 24;               // octet base lane (0,8,16,24)
    const int q  = r;                          // channel-eighth (8 ch)
    const int pl = threadIdx.x >> 3;           // local point 0..31
    const int p  = blockIdx.x * PTS_PER_BLK + pl;  // output-linear voxel

    const int z = p & (NZv - 1);
    const int y = (p >> 3) & (NYv - 1);
    const int x = p >> 10;
    const int n = (z * NYv + y) * NXv + x;

    const float pxw = __ldg(points + n * 3 + 0);
    const float pyw = __ldg(points + n * 3 + 1);
    const float pzw = __ldg(points + n * 3 + 2);

    // --- Projection: this lane computes ONE view (r<6; lanes 6,7 dup view 0)
    unsigned my_off, my_w0, my_w1;
    {
        const int vm = (r < 6) ? r : 0;
        const float* M = &sM[vm * 16];
        const float cx = fmaf(M[0], pxw, fmaf(M[1], pyw, fmaf(M[2],  pzw, M[3])));
        const float cy = fmaf(M[4], pxw, fmaf(M[5], pyw, fmaf(M[6],  pzw, M[7])));
        const float d  = fmaf(M[8], pxw, fmaf(M[9], pyw, fmaf(M[10], pzw, M[11])));

        const float ds = (fabsf(d) > 1e-6f) ? d : 1e-6f;
        const float rr = __fdividef(1.0f, ds);
        const float u  = cx * rr;
        const float vv = cy * rr;

        const bool valid = (d > 0.0f) & (u > 0.0f) & (u < IMG_W)
                                      & (vv > 0.0f) & (vv < IMG_H);

        // Exact power-of-2 scale: WF/IMG_W = HF/IMG_H = 0.125
        const float fx = fmaf(u,  0.125f, -0.5f);
        const float fy = fmaf(vv, 0.125f, -0.5f);
        const float x0f = floorf(fx);
        const float y0f = floorf(fy);
        const int x0 = (int)x0f;
        const int y0 = (int)y0f;
        const float wx1 = fx - x0f;
        const float wy1 = fy - y0f;

        // Base clamped so all 4 taps are in-bounds; edge handling folded
        // into weights (identical to zero-padded bilinear).
        const int bx = min(max(x0, 0), WFv - 2);
        const int by = min(max(y0, 0), HFv - 2);
        float wl = (x0 < 0) ? wx1 : ((x0 >= WFv - 1) ? 0.0f : 1.0f - wx1);
        float wr = (x0 < 0) ? 0.0f : ((x0 >= WFv - 1) ? 1.0f - wx1 : wx1);
        float wt = (y0 < 0) ? wy1 : ((y0 >= HFv - 1) ? 0.0f : 1.0f - wy1);
        float wb = (y0 < 0) ? 0.0f : ((y0 >= HFv - 1) ? 1.0f - wy1 : wy1);

        const __half2 h0 = __floats2half2_rn(wl * wt, wr * wt); // (w00, w10)
        const __half2 h1 = __floats2half2_rn(wl * wb, wr * wb); // (w01, w11)

        my_off = valid ? (unsigned)((vm * FEAT_HW + by * WFv + bx) * NCH)
                       : 0xFFFFFFFFu;
        my_w0  = *(const unsigned*)&h0;
        my_w1  = *(const unsigned*)&h1;
    }

    float acc[8];
#pragma unroll
    for (int i = 0; i < 8; i++) acc[i] = 0.0f;
    int cnt = 0;

    const int coff = q * 8;   // channel offset in halves (16B-aligned)

#pragma unroll 1
    for (int v = 0; v < NVIEW; v++) {
        const int src = obase + v;
        const unsigned off = __shfl_sync(0xFFFFFFFFu, my_off, src);
        const unsigned w0p = __shfl_sync(0xFFFFFFFFu, my_w0, src);
        const unsigned w1p = __shfl_sync(0xFFFFFFFFu, my_w1, src);

        if (off == 0xFFFFFFFFu) continue;

        const __half* bp = g_feat_h + off + coff;

        const uint4 t00 = __ldg((const uint4*)(bp));
        const uint4 t10 = __ldg((const uint4*)(bp + NCH));
        const uint4 t01 = __ldg((const uint4*)(bp + WFv * NCH));
        const uint4 t11 = __ldg((const uint4*)(bp + (WFv + 1) * NCH));

        const __half2 wp0 = *(const __half2*)&w0p;   // (w00, w10)
        const __half2 wp1 = *(const __half2*)&w1p;   // (w01, w11)
        const __half2 hw00 = __low2half2(wp0);
        const __half2 hw10 = __high2half2(wp0);
        const __half2 hw01 = __low2half2(wp1);
        const __half2 hw11 = __high2half2(wp1);

        const __half2* f00 = (const __half2*)&t00;
        const __half2* f10 = (const __half2*)&t10;
        const __half2* f01 = (const __half2*)&t01;
        const __half2* f11 = (const __half2*)&t11;
#pragma unroll
        for (int k = 0; k < 4; k++) {
            __half2 s = __hmul2(f00[k], hw00);
            s = __hfma2(f10[k], hw10, s);
            s = __hfma2(f01[k], hw01, s);
            s = __hfma2(f11[k], hw11, s);
            const float2 sf = __half22float2(s);
            acc[2 * k + 0] += sf.x;
            acc[2 * k + 1] += sf.y;
        }
        cnt++;
    }

    // Stage normalized result in SMEM
    const float inv = (cnt > 0) ? (1.0f / (float)cnt) : 0.0f;
#pragma unroll
    for (int j = 0; j < 8; j++) {
        s_out[pl * 65 + coff + j] = acc[j] * inv;
    }
    __syncthreads();

    // Coalesced write-out: 2048 floats; 32 consecutive p per channel = 128B
    const int p0 = blockIdx.x * PTS_PER_BLK;
#pragma unroll
    for (int jj = 0; jj < 8; jj++) {
        const int idx = threadIdx.x + jj * 256;   // 0..2047
        const int c   = idx >> 5;                 // 0..63
        const int ppl = idx & 31;                 // 0..31
        out[(size_t)c * NVOX + p0 + ppl] = s_out[ppl * 65 + c];
    }
}

extern "C" void kernel_launch(void* const* d_in, const int* in_sizes, int n_in,
                              void* d_out, int out_size)
{
    const float* x_fov  = (const float*)d_in[0];  // [1,6,64,116,200]
    const float* points = (const float*)d_in[1];  // [131072,3]
    const float* proj   = (const float*)d_in[2];  // [6,4,4]
    float* out = (float*)d_out;                   // [1,64,128,128,8]

    {
        dim3 blk(256);
        dim3 grd((WFv + 31) / 32, NVIEW * HFv);   // (7, 696)
        convert_kernel<<<grd, blk>>>(x_fov);
    }
    {
        const int blocks = NVOX / PTS_PER_BLK;    // 4096
        gather_kernel<<<blocks, 256>>>(points, proj, out);
    }
}